// round 4
// baseline (speedup 1.0000x reference)
#include <cuda_runtime.h>
#include <math.h>

// ---------------- static problem constants ----------------
#define BGR 4
#define NN  40962
#define DEG 6
#define E0C (BGR * NN * DEG)          // 983052
#define M0  (BGR * NN)                // 163848

static const int NIN[4] = {40962, 20481, 10241, 5121};   // nodes/graph entering layer i
static const int KK [4] = {20481, 10241,  5121, 2561};   // kept/graph after pool i

// ---------------- device scratch (static, no allocation) ----------------
__device__ __align__(128) float    g_H  [5243392];
__device__ __align__(128) float    g_XB [5243392];
__device__ __align__(128) float    g_XA [2621952];
__device__ float    g_deg[M0];
__device__ float    g_score[M0];
__device__ unsigned g_key[M0];
__device__ int      g_remap[M0];
__device__ int      g_srcbuf[2 * E0C];
__device__ int      g_dstbuf[2 * E0C];
__device__ int      g_ecnt[2];
__device__ int      g_E0cnt = E0C;
__device__ unsigned g_hist16[BGR * 65536];
__device__ unsigned g_prefix16[BGR];
__device__ int      g_want2[BGR];
__device__ unsigned g_thresh[BGR];
__device__ int      g_allow[BGR];
__device__ int      g_cntKeep[BGR];
__device__ int      g_cntEq[BGR];
__device__ float    g_pinv[4];
__device__ float    g_pmax[32 * 128];
__device__ float    g_psum[32 * 128];

// ---------------- helpers ----------------
__device__ __forceinline__ unsigned long long pack2(float a, float b) {
    unsigned long long r;
    asm("mov.b64 %0,{%1,%2};" : "=l"(r) : "f"(a), "f"(b));
    return r;
}
__device__ __forceinline__ void unpack2(unsigned long long v, float& a, float& b) {
    asm("mov.b64 {%0,%1},%2;" : "=f"(a), "=f"(b) : "l"(v));
}
__device__ __forceinline__ void ffma2(unsigned long long& acc, unsigned long long x,
                                      unsigned long long w) {
    asm("fma.rn.f32x2 %0,%1,%2,%0;" : "+l"(acc) : "l"(x), "l"(w));
}
__device__ __forceinline__ void red4(float* p, float4 v) {
    asm volatile("red.global.add.v4.f32 [%0],{%1,%2,%3,%4};"
                 :: "l"(p), "f"(v.x), "f"(v.y), "f"(v.z), "f"(v.w) : "memory");
}

// ---------------- kernels ----------------
// prep: zero layer-0 deg + hist16, compute pinv[4] = 1/||p_i||
__global__ void k_prep(const float* __restrict__ p1, const float* __restrict__ p2,
                       const float* __restrict__ p3, const float* __restrict__ p4,
                       float* __restrict__ pinv, float* __restrict__ deg,
                       unsigned* __restrict__ hist) {
    int gt = blockIdx.x * blockDim.x + threadIdx.x;
    int gs = gridDim.x * blockDim.x;
    for (int i = gt; i < M0; i += gs) deg[i] = 0.f;
    for (int i = gt; i < BGR * 65536; i += gs) hist[i] = 0u;
    if (blockIdx.x < 4 && threadIdx.x < 32) {
        const float* p = (blockIdx.x == 0) ? p1 : (blockIdx.x == 1) ? p2
                         : (blockIdx.x == 2) ? p3 : p4;
        int len = (blockIdx.x == 0) ? 32 : (blockIdx.x == 1) ? 64 : 128;
        float acc = 0.f;
        for (int f = threadIdx.x; f < len; f += 32) { float v = p[f]; acc += v * v; }
#pragma unroll
        for (int o = 16; o; o >>= 1) acc += __shfl_down_sync(0xffffffffu, acc, o);
        if (threadIdx.x == 0) pinv[blockIdx.x] = rsqrtf(acc);
    }
}

__global__ void k_deg0(const int* __restrict__ dst, float* __restrict__ deg) {
    int e = blockIdx.x * blockDim.x + threadIdx.x;
    if (e < E0C) atomicAdd(&deg[dst[e]], 1.0f);
}

// smem-tiled matmul: H = XB = (X@W) * dinv[m]   (self-loop pre-init, norm pre-scaled)
template <int FI, int FO>
__global__ void k_mm(const float* __restrict__ X, const float* __restrict__ W,
                     const float* __restrict__ deg, float* __restrict__ H,
                     float* __restrict__ XB, int M) {
    constexpr int J = FO / 4;       // threads per row
    constexpr int G = 256 / J;      // rows per block
    __shared__ float sX[G * FI];
    int r0 = blockIdx.x * G;
    for (int idx = threadIdx.x; idx < G * FI; idx += 256) {
        int r = r0 + idx / FI;
        sX[idx] = (r < M) ? X[(size_t)r * FI + (idx % FI)] : 0.f;
    }
    __syncthreads();
    int g = threadIdx.x / J, j = (threadIdx.x % J) * 4;
    int m = r0 + g;
    if (m >= M) return;
    const float* xr = sX + g * FI;
    unsigned long long acc0 = 0ull, acc1 = 0ull;
#pragma unroll
    for (int kq = 0; kq < FI; kq++) {
        float xv = xr[kq];
        unsigned long long xx = pack2(xv, xv);
        ulonglong2 wv = *(const ulonglong2*)(W + kq * FO + j);
        ffma2(acc0, xx, wv.x);
        ffma2(acc1, xx, wv.y);
    }
    float a0, a1, a2, a3;
    unpack2(acc0, a0, a1);
    unpack2(acc1, a2, a3);
    float dv = rsqrtf(deg[m] + 1.0f);
    float4 hv = make_float4(a0 * dv, a1 * dv, a2 * dv, a3 * dv);
    *(float4*)(H + (size_t)m * FO + j) = hv;
    *(float4*)(XB + (size_t)m * FO + j) = hv;
}

// edge aggregation: XB[d] += H'[s], thread per (edge, 4-feature chunk), v4 RED
template <int FO>
__global__ void k_agg(const int* __restrict__ src, const int* __restrict__ dst,
                      const int* __restrict__ ecnt, const float* __restrict__ H,
                      float* __restrict__ XB) {
    constexpr int LC = (FO == 32) ? 3 : (FO == 64) ? 4 : 5;   // log2(FO/4)
    constexpr int CM = (1 << LC) - 1;
    int total = (*ecnt) << LC;
    int t = blockIdx.x * blockDim.x + threadIdx.x;
    int stride = gridDim.x * blockDim.x;
    for (int i = t; i < total; i += stride) {
        int e = i >> LC, c = i & CM;
        int s = src[e], d = dst[e];
        float4 h = *(const float4*)(H + (size_t)s * FO + c * 4);
        red4(XB + (size_t)d * FO + c * 4, h);
    }
}

// fused: v = XB*dinv + b, relu (in place), score, key, pass-1 16-bit histogram
template <int FO>
__global__ void k_score(float* __restrict__ XB, const float* __restrict__ deg,
                        const float* __restrict__ bias, const float* __restrict__ p,
                        int M, int n, float* __restrict__ score,
                        unsigned* __restrict__ key, unsigned* __restrict__ hist) {
    int gw = (blockIdx.x * blockDim.x + threadIdx.x) >> 5;
    int lane = threadIdx.x & 31;
    if (gw >= M) return;
    int m = gw;
    float dv = rsqrtf(deg[m] + 1.0f);
    float acc = 0.f;
#pragma unroll
    for (int f = lane; f < FO; f += 32) {
        float v = XB[(size_t)m * FO + f] * dv + bias[f];
        v = fmaxf(v, 0.f);
        XB[(size_t)m * FO + f] = v;
        acc += v * p[f];
    }
#pragma unroll
    for (int o = 16; o; o >>= 1) acc += __shfl_down_sync(0xffffffffu, acc, o);
    if (lane == 0) {
        score[m] = acc;
        unsigned u = __float_as_uint(acc);
        unsigned kk = (u & 0x80000000u) ? ~u : (u | 0x80000000u);
        key[m] = kk;
        int b = m / n;
        atomicAdd(&hist[b * 65536 + (kk >> 16)], 1u);
    }
}

// scan pass 1: find top-16-bit threshold bin per graph, zero the histogram
__global__ void k_scan1(unsigned* __restrict__ hist, int k,
                        unsigned* __restrict__ prefix16, int* __restrict__ want2) {
    __shared__ unsigned arr[1024];
    int b = blockIdx.x, t = threadIdx.x;
    unsigned* hb = hist + b * 65536;
    unsigned s = 0;
#pragma unroll 8
    for (int i = 0; i < 64; i++) s += hb[t * 64 + i];
    arr[t] = s;
    __syncthreads();
    for (int off = 1; off < 1024; off <<= 1) {
        unsigned v = (t + off < 1024) ? arr[t + off] : 0u;
        __syncthreads();
        arr[t] += v;
        __syncthreads();
    }
    unsigned above = arr[t] - s;   // keys in chunks strictly above mine
    if (above < (unsigned)k && above + s >= (unsigned)k) {
        unsigned cum = above;
        for (int i = 63; i >= 0; i--) {
            unsigned h = hb[t * 64 + i];
            if (cum + h >= (unsigned)k) {
                prefix16[b] = (unsigned)(t * 64 + i);
                want2[b] = k - (int)cum;
                break;
            }
            cum += h;
        }
    }
    for (int i = 0; i < 64; i++) hb[t * 64 + i] = 0u;
}

// pass-2 histogram on low 16 bits of keys matching the prefix
__global__ void k_hist2(const unsigned* __restrict__ key, int M, int n,
                        const unsigned* __restrict__ prefix16, unsigned* __restrict__ hist) {
    int m = blockIdx.x * blockDim.x + threadIdx.x;
    if (m >= M) return;
    unsigned kk = key[m];
    int b = m / n;
    if ((kk >> 16) == prefix16[b]) atomicAdd(&hist[b * 65536 + (kk & 0xffffu)], 1u);
}

// scan pass 2: final threshold + allow; zero hist + counters + next deg + next ecnt
__global__ void k_scan2(unsigned* __restrict__ hist, const unsigned* __restrict__ prefix16,
                        const int* __restrict__ want2, unsigned* __restrict__ thresh,
                        int* __restrict__ allow, int* __restrict__ cntK, int* __restrict__ cntE,
                        float* __restrict__ degN, int MN, int* __restrict__ eCn) {
    __shared__ unsigned arr[1024];
    int b = blockIdx.x, t = threadIdx.x;
    unsigned* hb = hist + b * 65536;
    int w = want2[b];
    unsigned s = 0;
#pragma unroll 8
    for (int i = 0; i < 64; i++) s += hb[t * 64 + i];
    arr[t] = s;
    __syncthreads();
    for (int off = 1; off < 1024; off <<= 1) {
        unsigned v = (t + off < 1024) ? arr[t + off] : 0u;
        __syncthreads();
        arr[t] += v;
        __syncthreads();
    }
    unsigned above = arr[t] - s;
    if (above < (unsigned)w && above + s >= (unsigned)w) {
        unsigned cum = above;
        for (int i = 63; i >= 0; i--) {
            unsigned h = hb[t * 64 + i];
            if (cum + h >= (unsigned)w) {
                thresh[b] = (prefix16[b] << 16) | (unsigned)(t * 64 + i);
                allow[b] = w - (int)cum;
                break;
            }
            cum += h;
        }
    }
    for (int i = 0; i < 64; i++) hb[t * 64 + i] = 0u;
    if (t == 0) {
        cntK[b] = 0;
        cntE[b] = 0;
        if (b == 0) *eCn = 0;
    }
    for (int i = b * 1024 + t; i < MN; i += 4096) degN[i] = 0.f;
}

// fused compact + gather: warp per old node
template <int FO>
__global__ void k_cg(const unsigned* __restrict__ key, const float* __restrict__ score,
                     const float* __restrict__ XB, int M, int n, int k,
                     const unsigned* __restrict__ thresh, const int* __restrict__ allow,
                     int* __restrict__ cntK, int* __restrict__ cntE,
                     int* __restrict__ remap, const float* __restrict__ pinv,
                     float* __restrict__ XA) {
    int gw = (blockIdx.x * blockDim.x + threadIdx.x) >> 5;
    int lane = threadIdx.x & 31;
    if (gw >= M) return;
    int m = gw;
    int b = m / n;
    int nid = -1;
    if (lane == 0) {
        unsigned kk = key[m], t = thresh[b];
        bool keep = kk > t;
        if (!keep && kk == t) keep = (atomicAdd(&cntE[b], 1) < allow[b]);
        if (keep) nid = b * k + atomicAdd(&cntK[b], 1);
        remap[m] = nid;
    }
    nid = __shfl_sync(0xffffffffu, nid, 0);
    if (nid >= 0) {
        float t = tanhf(score[m] * (*pinv));
#pragma unroll
        for (int f = lane; f < FO; f += 32)
            XA[(size_t)nid * FO + f] = XB[(size_t)m * FO + f] * t;
    }
}

// fused edge remap/compact + next-layer degree count
__global__ void k_eremap(const int* __restrict__ srcO, const int* __restrict__ dstO,
                         const int* __restrict__ ecntO, const int* __restrict__ remap,
                         int* __restrict__ srcN, int* __restrict__ dstN,
                         int* __restrict__ ecntN, float* __restrict__ degN) {
    int E = *ecntO;
    int gt = blockIdx.x * blockDim.x + threadIdx.x;
    int stride = gridDim.x * blockDim.x;
    for (int e = gt; e < E; e += stride) {
        int s = remap[srcO[e]], d = remap[dstO[e]];
        if (s >= 0 && d >= 0) {
            int pos = atomicAdd(ecntN, 1);
            srcN[pos] = s;
            dstN[pos] = d;
            atomicAdd(&degN[d], 1.f);
        }
    }
}

// readout part 1: partial max/sum over row slices (8 slices per graph)
__global__ void k_read1(const float* __restrict__ X, float* __restrict__ pmax,
                        float* __restrict__ psum, int kn) {
    int b = blockIdx.x >> 3, s = blockIdx.x & 7, f = threadIdx.x;   // 128 threads
    int per = (kn + 7) / 8;
    int i0 = s * per, i1 = min(kn, i0 + per);
    float mx = -3.4e38f, sm = 0.f;
    const float* base = X + (size_t)b * kn * 128 + f;
    for (int i = i0; i < i1; i++) {
        float v = base[(size_t)i * 128];
        mx = fmaxf(mx, v);
        sm += v;
    }
    pmax[blockIdx.x * 128 + f] = mx;
    psum[blockIdx.x * 128 + f] = sm;
}

// readout part 2: final reduce + metadata conv + fc + fc2
__global__ void k_read2(const float* __restrict__ pmax, const float* __restrict__ psum,
                        const float* __restrict__ meta, const float* __restrict__ cw,
                        const float* __restrict__ cb, const float* __restrict__ fcw,
                        const float* __restrict__ fcb, const float* __restrict__ fc2w,
                        const float* __restrict__ fc2b, float* __restrict__ out, int kn) {
    __shared__ float v[260];
    __shared__ float red[128];
    int b = blockIdx.x, f = threadIdx.x;   // 128 threads
    float mx = -3.4e38f, sm = 0.f;
#pragma unroll
    for (int s = 0; s < 8; s++) {
        mx = fmaxf(mx, pmax[(b * 8 + s) * 128 + f]);
        sm += psum[(b * 8 + s) * 128 + f];
    }
    v[f] = mx;
    v[128 + f] = sm / (float)kn;
    if (f < 4) {
        float mv = meta[b] * cw[f] + cb[f];
        v[256 + f] = mv > 0.f ? mv : 0.f;
    }
    __syncthreads();
    float acc = fcb[f];
    for (int i = 0; i < 260; i++) acc += v[i] * fcw[i * 128 + f];
    float hv = acc > 0.f ? acc : 0.f;
    red[f] = hv * fc2w[f];
    __syncthreads();
    for (int s = 64; s > 0; s >>= 1) {
        if (f < s) red[f] += red[f + s];
        __syncthreads();
    }
    if (f == 0) out[b] = red[0] + fc2b[0];
}

// ---------------- host orchestration ----------------
static inline int gdiv(int n, int t) { return (n + t - 1) / t; }

extern "C" void kernel_launch(void* const* d_in, const int* in_sizes, int n_in,
                              void* d_out, int out_size) {
    const float* x0   = (const float*)d_in[0];
    const int*   ei   = (const int*)  d_in[1];
    const float* meta = (const float*)d_in[2];
    const float* W[4]  = {(const float*)d_in[3], (const float*)d_in[6],
                          (const float*)d_in[9], (const float*)d_in[12]};
    const float* bb[4] = {(const float*)d_in[4], (const float*)d_in[7],
                          (const float*)d_in[10], (const float*)d_in[13]};
    const float* pp[4] = {(const float*)d_in[5], (const float*)d_in[8],
                          (const float*)d_in[11], (const float*)d_in[14]};
    const float* cw   = (const float*)d_in[15];
    const float* cb   = (const float*)d_in[16];
    const float* fcw  = (const float*)d_in[17];
    const float* fcb  = (const float*)d_in[18];
    const float* fc2w = (const float*)d_in[19];
    const float* fc2b = (const float*)d_in[20];
    float* out = (float*)d_out;

    float *H, *XB, *XA, *deg, *score, *pinv, *pmax, *psum;
    unsigned *key, *thresh, *hist, *prefix16;
    int *remap, *allow, *cntK, *cntE, *srcb, *dstb, *ecnt, *e0c, *want2;
    cudaGetSymbolAddress((void**)&H, g_H);
    cudaGetSymbolAddress((void**)&XB, g_XB);
    cudaGetSymbolAddress((void**)&XA, g_XA);
    cudaGetSymbolAddress((void**)&deg, g_deg);
    cudaGetSymbolAddress((void**)&score, g_score);
    cudaGetSymbolAddress((void**)&key, g_key);
    cudaGetSymbolAddress((void**)&remap, g_remap);
    cudaGetSymbolAddress((void**)&srcb, g_srcbuf);
    cudaGetSymbolAddress((void**)&dstb, g_dstbuf);
    cudaGetSymbolAddress((void**)&ecnt, g_ecnt);
    cudaGetSymbolAddress((void**)&e0c, g_E0cnt);
    cudaGetSymbolAddress((void**)&hist, g_hist16);
    cudaGetSymbolAddress((void**)&prefix16, g_prefix16);
    cudaGetSymbolAddress((void**)&want2, g_want2);
    cudaGetSymbolAddress((void**)&thresh, g_thresh);
    cudaGetSymbolAddress((void**)&allow, g_allow);
    cudaGetSymbolAddress((void**)&cntK, g_cntKeep);
    cudaGetSymbolAddress((void**)&cntE, g_cntEq);
    cudaGetSymbolAddress((void**)&pinv, g_pinv);
    cudaGetSymbolAddress((void**)&pmax, g_pmax);
    cudaGetSymbolAddress((void**)&psum, g_psum);

    const int T = 256;

    k_prep<<<512, T>>>(pp[0], pp[1], pp[2], pp[3], pinv, deg, hist);
    k_deg0<<<gdiv(E0C, T), T>>>(ei + E0C, deg);

    for (int i = 0; i < 4; i++) {
        int n = NIN[i], M = BGR * n, k = KK[i];
        const float* Xin = i ? XA : x0;
        const int* eS = i ? (srcb + ((i + 1) & 1) * E0C) : ei;
        const int* eD = i ? (dstb + ((i + 1) & 1) * E0C) : (ei + E0C);
        const int* eC = i ? (ecnt + ((i + 1) & 1)) : e0c;
        int* eSn = srcb + (i & 1) * E0C;
        int* eDn = dstb + (i & 1) * E0C;
        int* eCn = ecnt + (i & 1);

        // 1. H' = XB = (X@W)*dinv (smem-tiled)
        switch (i) {
            case 0: k_mm<4, 32>   <<<gdiv(M, 32), T>>>(Xin, W[0], deg, H, XB, M); break;
            case 1: k_mm<32, 64>  <<<gdiv(M, 16), T>>>(Xin, W[1], deg, H, XB, M); break;
            case 2: k_mm<64, 128> <<<gdiv(M, 8),  T>>>(Xin, W[2], deg, H, XB, M); break;
            case 3: k_mm<128, 128><<<gdiv(M, 8),  T>>>(Xin, W[3], deg, H, XB, M); break;
        }
        // 2. aggregate: XB[d] += H'[s] (v4 vector RED)
        int aggGrid = (i == 0) ? gdiv(E0C * 8, T) : 4096;
        switch (i) {
            case 0: k_agg<32> <<<aggGrid, T>>>(eS, eD, eC, H, XB); break;
            case 1: k_agg<64> <<<aggGrid, T>>>(eS, eD, eC, H, XB); break;
            case 2: k_agg<128><<<aggGrid, T>>>(eS, eD, eC, H, XB); break;
            case 3: k_agg<128><<<aggGrid, T>>>(eS, eD, eC, H, XB); break;
        }
        // 3. finalize (dinv + bias + relu) + score + key + pass-1 histogram
        switch (i) {
            case 0: k_score<32> <<<gdiv(M * 32, T), T>>>(XB, deg, bb[0], pp[0], M, n, score, key, hist); break;
            case 1: k_score<64> <<<gdiv(M * 32, T), T>>>(XB, deg, bb[1], pp[1], M, n, score, key, hist); break;
            case 2: k_score<128><<<gdiv(M * 32, T), T>>>(XB, deg, bb[2], pp[2], M, n, score, key, hist); break;
            case 3: k_score<128><<<gdiv(M * 32, T), T>>>(XB, deg, bb[3], pp[3], M, n, score, key, hist); break;
        }
        // 4. 2-pass 16-bit radix select (parallel)
        int MN = (i < 3) ? BGR * k : 0;
        k_scan1<<<BGR, 1024>>>(hist, k, prefix16, want2);
        k_hist2<<<gdiv(M, T), T>>>(key, M, n, prefix16, hist);
        k_scan2<<<BGR, 1024>>>(hist, prefix16, want2, thresh, allow, cntK, cntE, deg, MN, eCn);
        // 5. compact + gather (fused)
        switch (i) {
            case 0: k_cg<32> <<<gdiv(M * 32, T), T>>>(key, score, XB, M, n, k, thresh, allow,
                                                      cntK, cntE, remap, pinv + 0, XA); break;
            case 1: k_cg<64> <<<gdiv(M * 32, T), T>>>(key, score, XB, M, n, k, thresh, allow,
                                                      cntK, cntE, remap, pinv + 1, XA); break;
            case 2: k_cg<128><<<gdiv(M * 32, T), T>>>(key, score, XB, M, n, k, thresh, allow,
                                                      cntK, cntE, remap, pinv + 2, XA); break;
            case 3: k_cg<128><<<gdiv(M * 32, T), T>>>(key, score, XB, M, n, k, thresh, allow,
                                                      cntK, cntE, remap, pinv + 3, XA); break;
        }
        // 6. edge remap + next-layer degree (fused)
        if (i < 3) {
            int erGrid = (i == 0) ? gdiv(E0C, T) : 2048;
            k_eremap<<<erGrid, T>>>(eS, eD, eC, remap, eSn, eDn, eCn, deg);
        }
    }

    // readout
    k_read1<<<BGR * 8, 128>>>(XA, pmax, psum, KK[3]);
    k_read2<<<BGR, 128>>>(pmax, psum, meta, cw, cb, fcw, fcb, fc2w, fc2b, out, KK[3]);
    (void)in_sizes; (void)n_in; (void)out_size;
}

// round 6
// speedup vs baseline: 2.1384x; 2.1384x over previous
#include <cuda_runtime.h>
#include <math.h>

// ---------------- static problem constants ----------------
#define BGR 4
#define NN  40962
#define DEG 6
#define E0C (BGR * NN * DEG)          // 983052
#define M0  (BGR * NN)                // 163848

static const int NIN[4] = {40962, 20481, 10241, 5121};   // nodes/graph entering layer i
static const int KK [4] = {20481, 10241,  5121, 2561};   // kept/graph after pool i

// ---------------- device scratch (static, no allocation) ----------------
__device__ __align__(128) float    g_H  [5243392];
__device__ __align__(128) float    g_XB [5243392];
__device__ __align__(128) float    g_XA [2621952];
__device__ float    g_deg[M0];
__device__ float    g_score[M0];
__device__ unsigned g_key[M0];
__device__ int      g_remap[M0];
__device__ int      g_srcbuf[2 * E0C];
__device__ int      g_dstbuf[2 * E0C];
__device__ int      g_ecnt[2];
__device__ int      g_E0cnt = E0C;
__device__ unsigned g_thresh[BGR];
__device__ int      g_allow[BGR];
__device__ int      g_cntKeep[BGR];
__device__ int      g_cntEq[BGR];
__device__ float    g_pinv[4];
__device__ float    g_pmax[32 * 128];
__device__ float    g_psum[32 * 128];

// ---------------- helpers ----------------
__device__ __forceinline__ unsigned long long pack2(float a, float b) {
    unsigned long long r;
    asm("mov.b64 %0,{%1,%2};" : "=l"(r) : "f"(a), "f"(b));
    return r;
}
__device__ __forceinline__ void unpack2(unsigned long long v, float& a, float& b) {
    asm("mov.b64 {%0,%1},%2;" : "=f"(a), "=f"(b) : "l"(v));
}
__device__ __forceinline__ void ffma2(unsigned long long& acc, unsigned long long x,
                                      unsigned long long w) {
    asm("fma.rn.f32x2 %0,%1,%2,%0;" : "+l"(acc) : "l"(x), "l"(w));
}
__device__ __forceinline__ void red4(float* p, float4 v) {
    asm volatile("red.global.add.v4.f32 [%0],{%1,%2,%3,%4};"
                 :: "l"(p), "f"(v.x), "f"(v.y), "f"(v.z), "f"(v.w) : "memory");
}

// ---------------- kernels ----------------
// prep: zero layer-0 deg, compute pinv[4] = 1/||p_i||
__global__ void k_prep(const float* __restrict__ p1, const float* __restrict__ p2,
                       const float* __restrict__ p3, const float* __restrict__ p4,
                       float* __restrict__ pinv, float* __restrict__ deg) {
    int gt = blockIdx.x * blockDim.x + threadIdx.x;
    int gs = gridDim.x * blockDim.x;
    for (int i = gt; i < M0; i += gs) deg[i] = 0.f;
    if (blockIdx.x < 4 && threadIdx.x < 32) {
        const float* p = (blockIdx.x == 0) ? p1 : (blockIdx.x == 1) ? p2
                         : (blockIdx.x == 2) ? p3 : p4;
        int len = (blockIdx.x == 0) ? 32 : (blockIdx.x == 1) ? 64 : 128;
        float acc = 0.f;
        for (int f = threadIdx.x; f < len; f += 32) { float v = p[f]; acc += v * v; }
#pragma unroll
        for (int o = 16; o; o >>= 1) acc += __shfl_down_sync(0xffffffffu, acc, o);
        if (threadIdx.x == 0) pinv[blockIdx.x] = rsqrtf(acc);
    }
}

__global__ void k_deg0(const int* __restrict__ dst, float* __restrict__ deg) {
    int e = blockIdx.x * blockDim.x + threadIdx.x;
    if (e < E0C) atomicAdd(&deg[dst[e]], 1.0f);
}

// smem-tiled matmul: H = XB = (X@W) * dinv[m]   (norm pre-scaled into H')
template <int FI, int FO>
__global__ void k_mm(const float* __restrict__ X, const float* __restrict__ W,
                     const float* __restrict__ deg, float* __restrict__ H,
                     float* __restrict__ XB, int M) {
    constexpr int J = FO / 4;       // threads per row
    constexpr int G = 256 / J;      // rows per block
    __shared__ float sX[G * FI];
    int r0 = blockIdx.x * G;
    for (int idx = threadIdx.x; idx < G * FI; idx += 256) {
        int r = r0 + idx / FI;
        sX[idx] = (r < M) ? X[(size_t)r * FI + (idx % FI)] : 0.f;
    }
    __syncthreads();
    int g = threadIdx.x / J, j = (threadIdx.x % J) * 4;
    int m = r0 + g;
    if (m >= M) return;
    const float* xr = sX + g * FI;
    unsigned long long acc0 = 0ull, acc1 = 0ull;
#pragma unroll
    for (int kq = 0; kq < FI; kq++) {
        float xv = xr[kq];
        unsigned long long xx = pack2(xv, xv);
        ulonglong2 wv = *(const ulonglong2*)(W + kq * FO + j);
        ffma2(acc0, xx, wv.x);
        ffma2(acc1, xx, wv.y);
    }
    float a0, a1, a2, a3;
    unpack2(acc0, a0, a1);
    unpack2(acc1, a2, a3);
    float dv = rsqrtf(deg[m] + 1.0f);
    float4 hv = make_float4(a0 * dv, a1 * dv, a2 * dv, a3 * dv);
    *(float4*)(H + (size_t)m * FO + j) = hv;
    *(float4*)(XB + (size_t)m * FO + j) = hv;
}

// edge aggregation: XB[d] += H'[s], thread per (edge, 4-feature chunk), v4 RED
template <int FO>
__global__ void k_agg(const int* __restrict__ src, const int* __restrict__ dst,
                      const int* __restrict__ ecnt, const float* __restrict__ H,
                      float* __restrict__ XB) {
    constexpr int LC = (FO == 32) ? 3 : (FO == 64) ? 4 : 5;   // log2(FO/4)
    constexpr int CM = (1 << LC) - 1;
    int total = (*ecnt) << LC;
    int t = blockIdx.x * blockDim.x + threadIdx.x;
    int stride = gridDim.x * blockDim.x;
    for (int i = t; i < total; i += stride) {
        int e = i >> LC, c = i & CM;
        int s = src[e], d = dst[e];
        float4 h = *(const float4*)(H + (size_t)s * FO + c * 4);
        red4(XB + (size_t)d * FO + c * 4, h);
    }
}

// fused finalize: v = XB*dinv + b, relu (in place), score, monotonic key
template <int FO>
__global__ void k_score(float* __restrict__ XB, const float* __restrict__ deg,
                        const float* __restrict__ bias, const float* __restrict__ p,
                        int M, float* __restrict__ score, unsigned* __restrict__ key) {
    int m = (blockIdx.x * blockDim.x + threadIdx.x) >> 5;
    int lane = threadIdx.x & 31;
    if (m >= M) return;
    float dv = rsqrtf(deg[m] + 1.0f);
    float acc = 0.f;
#pragma unroll
    for (int f = lane; f < FO; f += 32) {
        float v = XB[(size_t)m * FO + f] * dv + bias[f];
        v = fmaxf(v, 0.f);
        XB[(size_t)m * FO + f] = v;
        acc += v * p[f];
    }
#pragma unroll
    for (int o = 16; o; o >>= 1) acc += __shfl_down_sync(0xffffffffu, acc, o);
    if (lane == 0) {
        score[m] = acc;
        unsigned u = __float_as_uint(acc);
        key[m] = (u & 0x80000000u) ? ~u : (u | 0x80000000u);
    }
}

// single-kernel 4-pass radix select (1 block per graph); also zeroes counters,
// next-layer deg, and next-layer edge count
__global__ void k_select(const unsigned* __restrict__ key, int n, int k,
                         unsigned* __restrict__ thresh, int* __restrict__ allow,
                         int* __restrict__ cntK, int* __restrict__ cntE,
                         float* __restrict__ degN, int MN, int* __restrict__ eCn) {
    __shared__ unsigned hist[256];
    __shared__ unsigned sP;
    __shared__ int sW;
    int b = blockIdx.x;
    const unsigned* kb = key + b * n;
    unsigned prefix = 0;
    int want = k;
    for (int pass = 0; pass < 4; pass++) {
        for (int i = threadIdx.x; i < 256; i += blockDim.x) hist[i] = 0u;
        __syncthreads();
        int shp = 32 - 8 * pass, shd = 24 - 8 * pass;
        for (int i = threadIdx.x; i < n; i += blockDim.x) {
            unsigned kk = kb[i];
            if (pass == 0 || (kk >> shp) == prefix)
                atomicAdd(&hist[(kk >> shd) & 255u], 1u);
        }
        __syncthreads();
        if (threadIdx.x == 0) {
            unsigned cum = 0;
            int d = 255;
            for (;;) {
                unsigned h = hist[d];
                if (cum + h >= (unsigned)want || d == 0) break;
                cum += h;
                d--;
            }
            sP = (prefix << 8) | (unsigned)d;
            sW = want - (int)cum;
        }
        __syncthreads();
        prefix = sP;
        want = sW;
    }
    if (threadIdx.x == 0) {
        thresh[b] = prefix;
        allow[b] = want;
        cntK[b] = 0;
        cntE[b] = 0;
        if (b == 0) *eCn = 0;
    }
    for (int i = b * blockDim.x + threadIdx.x; i < MN; i += gridDim.x * blockDim.x)
        degN[i] = 0.f;
}

// fused compact + gather: lane per node; warp-uniform aggregation path with
// unconditional collectives (fixes round-5 divergent __shfl_sync hang)
template <int FO>
__global__ void k_cg(const unsigned* __restrict__ key, const float* __restrict__ score,
                     const float* __restrict__ XB, int M, int n, int k,
                     const unsigned* __restrict__ thresh, const int* __restrict__ allow,
                     int* __restrict__ cntK, int* __restrict__ cntE,
                     int* __restrict__ remap, const float* __restrict__ pinv,
                     float* __restrict__ XA) {
    int lane = threadIdx.x & 31;
    int base = ((blockIdx.x * blockDim.x + threadIdx.x) >> 5) << 5;  // first node of warp
    if (base >= M) return;                                           // warp-uniform
    int m = base + lane;
    bool active = (m < M);
    float pv = *pinv;

    int b = 0;
    bool keep = false;
    if (active) {
        b = m / n;
        unsigned kk = key[m], t = thresh[b];
        keep = kk > t;
        if (!keep && kk == t)                               // rare tie path
            keep = (atomicAdd(&cntE[b], 1) < allow[b]);
    }

    int nid = -1;
    // warp-uniform predicate: whole warp active and within one graph
    bool uniformWarp = (base + 31 < M) && ((base / n) == ((base + 31) / n));
    if (uniformWarp) {
        unsigned keepmask = __ballot_sync(0xffffffffu, keep);       // all lanes
        int leader = __ffs(keepmask) - 1;                           // -1 if none kept
        int basepos = 0;
        if (keep && lane == leader)
            basepos = atomicAdd(&cntK[b], __popc(keepmask));
        // unconditional shfl: safe dummy index 0 when keepmask==0 (value unused)
        basepos = __shfl_sync(0xffffffffu, basepos, (leader < 0) ? 0 : leader);
        if (keep)
            nid = b * k + basepos + __popc(keepmask & ((1u << lane) - 1u));
    } else {
        if (keep) nid = b * k + atomicAdd(&cntK[b], 1);             // few warps only
    }
    if (active) remap[m] = nid;

    float tv = keep ? tanhf(score[m] * pv) : 0.f;
    // warp loops over its 32 nodes; all lanes cooperate on each kept row
    unsigned fullkeep = __ballot_sync(0xffffffffu, keep);           // all lanes
#pragma unroll 1
    for (int r = 0; r < 32; r++) {
        if (!((fullkeep >> r) & 1u)) continue;                      // uniform
        int nid_r = __shfl_sync(0xffffffffu, nid, r);
        float t_r = __shfl_sync(0xffffffffu, tv, r);
        int m_r = base + r;
        if (lane < FO / 4) {
            float4 v = *(const float4*)(XB + (size_t)m_r * FO + lane * 4);
            v.x *= t_r; v.y *= t_r; v.z *= t_r; v.w *= t_r;
            *(float4*)(XA + (size_t)nid_r * FO + lane * 4) = v;
        }
    }
}

// edge remap/compact + next-layer degree; warp-aggregated ecntN atomic
__global__ void k_eremap(const int* __restrict__ srcO, const int* __restrict__ dstO,
                         const int* __restrict__ ecntO, const int* __restrict__ remap,
                         int* __restrict__ srcN, int* __restrict__ dstN,
                         int* __restrict__ ecntN, float* __restrict__ degN) {
    int E = *ecntO;
    int gt = blockIdx.x * blockDim.x + threadIdx.x;
    int lane = threadIdx.x & 31;
    int stride = gridDim.x * blockDim.x;
    for (int e = gt; __any_sync(0xffffffffu, e < E); e += stride) {
        bool in = (e < E);
        int s = -1, d = -1;
        if (in) {
            s = remap[srcO[e]];
            d = remap[dstO[e]];
        }
        bool valid = in && (s >= 0) && (d >= 0);
        unsigned mask = __ballot_sync(0xffffffffu, valid);          // warp-uniform
        if (!mask) continue;
        int leader = __ffs(mask) - 1;
        int basepos = 0;
        if (lane == leader) basepos = atomicAdd(ecntN, __popc(mask));
        basepos = __shfl_sync(0xffffffffu, basepos, leader);        // all lanes
        if (valid) {
            int pos = basepos + __popc(mask & ((1u << lane) - 1u));
            srcN[pos] = s;
            dstN[pos] = d;
            atomicAdd(&degN[d], 1.f);
        }
    }
}

// readout part 1: partial max/sum over row slices (8 slices per graph)
__global__ void k_read1(const float* __restrict__ X, float* __restrict__ pmax,
                        float* __restrict__ psum, int kn) {
    int b = blockIdx.x >> 3, s = blockIdx.x & 7, f = threadIdx.x;   // 128 threads
    int per = (kn + 7) / 8;
    int i0 = s * per, i1 = min(kn, i0 + per);
    float mx = -3.4e38f, sm = 0.f;
    const float* base = X + (size_t)b * kn * 128 + f;
    for (int i = i0; i < i1; i++) {
        float v = base[(size_t)i * 128];
        mx = fmaxf(mx, v);
        sm += v;
    }
    pmax[blockIdx.x * 128 + f] = mx;
    psum[blockIdx.x * 128 + f] = sm;
}

// readout part 2: final reduce + metadata conv + fc + fc2
__global__ void k_read2(const float* __restrict__ pmax, const float* __restrict__ psum,
                        const float* __restrict__ meta, const float* __restrict__ cw,
                        const float* __restrict__ cb, const float* __restrict__ fcw,
                        const float* __restrict__ fcb, const float* __restrict__ fc2w,
                        const float* __restrict__ fc2b, float* __restrict__ out, int kn) {
    __shared__ float v[260];
    __shared__ float red[128];
    int b = blockIdx.x, f = threadIdx.x;   // 128 threads
    float mx = -3.4e38f, sm = 0.f;
#pragma unroll
    for (int s = 0; s < 8; s++) {
        mx = fmaxf(mx, pmax[(b * 8 + s) * 128 + f]);
        sm += psum[(b * 8 + s) * 128 + f];
    }
    v[f] = mx;
    v[128 + f] = sm / (float)kn;
    if (f < 4) {
        float mv = meta[b] * cw[f] + cb[f];
        v[256 + f] = mv > 0.f ? mv : 0.f;
    }
    __syncthreads();
    float acc = fcb[f];
    for (int i = 0; i < 260; i++) acc += v[i] * fcw[i * 128 + f];
    float hv = acc > 0.f ? acc : 0.f;
    red[f] = hv * fc2w[f];
    __syncthreads();
    for (int s = 64; s > 0; s >>= 1) {
        if (f < s) red[f] += red[f + s];
        __syncthreads();
    }
    if (f == 0) out[b] = red[0] + fc2b[0];
}

// ---------------- host orchestration ----------------
static inline int gdiv(int n, int t) { return (n + t - 1) / t; }

extern "C" void kernel_launch(void* const* d_in, const int* in_sizes, int n_in,
                              void* d_out, int out_size) {
    const float* x0   = (const float*)d_in[0];
    const int*   ei   = (const int*)  d_in[1];
    const float* meta = (const float*)d_in[2];
    const float* W[4]  = {(const float*)d_in[3], (const float*)d_in[6],
                          (const float*)d_in[9], (const float*)d_in[12]};
    const float* bb[4] = {(const float*)d_in[4], (const float*)d_in[7],
                          (const float*)d_in[10], (const float*)d_in[13]};
    const float* pp[4] = {(const float*)d_in[5], (const float*)d_in[8],
                          (const float*)d_in[11], (const float*)d_in[14]};
    const float* cw   = (const float*)d_in[15];
    const float* cb   = (const float*)d_in[16];
    const float* fcw  = (const float*)d_in[17];
    const float* fcb  = (const float*)d_in[18];
    const float* fc2w = (const float*)d_in[19];
    const float* fc2b = (const float*)d_in[20];
    float* out = (float*)d_out;

    float *H, *XB, *XA, *deg, *score, *pinv, *pmax, *psum;
    unsigned *key, *thresh;
    int *remap, *allow, *cntK, *cntE, *srcb, *dstb, *ecnt, *e0c;
    cudaGetSymbolAddress((void**)&H, g_H);
    cudaGetSymbolAddress((void**)&XB, g_XB);
    cudaGetSymbolAddress((void**)&XA, g_XA);
    cudaGetSymbolAddress((void**)&deg, g_deg);
    cudaGetSymbolAddress((void**)&score, g_score);
    cudaGetSymbolAddress((void**)&key, g_key);
    cudaGetSymbolAddress((void**)&remap, g_remap);
    cudaGetSymbolAddress((void**)&srcb, g_srcbuf);
    cudaGetSymbolAddress((void**)&dstb, g_dstbuf);
    cudaGetSymbolAddress((void**)&ecnt, g_ecnt);
    cudaGetSymbolAddress((void**)&e0c, g_E0cnt);
    cudaGetSymbolAddress((void**)&thresh, g_thresh);
    cudaGetSymbolAddress((void**)&allow, g_allow);
    cudaGetSymbolAddress((void**)&cntK, g_cntKeep);
    cudaGetSymbolAddress((void**)&cntE, g_cntEq);
    cudaGetSymbolAddress((void**)&pinv, g_pinv);
    cudaGetSymbolAddress((void**)&pmax, g_pmax);
    cudaGetSymbolAddress((void**)&psum, g_psum);

    const int T = 256;

    k_prep<<<256, T>>>(pp[0], pp[1], pp[2], pp[3], pinv, deg);
    k_deg0<<<gdiv(E0C, T), T>>>(ei + E0C, deg);

    for (int i = 0; i < 4; i++) {
        int n = NIN[i], M = BGR * n, k = KK[i];
        const float* Xin = i ? XA : x0;
        const int* eS = i ? (srcb + ((i + 1) & 1) * E0C) : ei;
        const int* eD = i ? (dstb + ((i + 1) & 1) * E0C) : (ei + E0C);
        const int* eC = i ? (ecnt + ((i + 1) & 1)) : e0c;
        int* eSn = srcb + (i & 1) * E0C;
        int* eDn = dstb + (i & 1) * E0C;
        int* eCn = ecnt + (i & 1);

        // 1. H' = XB = (X@W)*dinv (smem-tiled)
        switch (i) {
            case 0: k_mm<4, 32>   <<<gdiv(M, 32), T>>>(Xin, W[0], deg, H, XB, M); break;
            case 1: k_mm<32, 64>  <<<gdiv(M, 16), T>>>(Xin, W[1], deg, H, XB, M); break;
            case 2: k_mm<64, 128> <<<gdiv(M, 8),  T>>>(Xin, W[2], deg, H, XB, M); break;
            case 3: k_mm<128, 128><<<gdiv(M, 8),  T>>>(Xin, W[3], deg, H, XB, M); break;
        }
        // 2. aggregate: XB[d] += H'[s] (v4 vector RED)
        int aggGrid = (i == 0) ? gdiv(E0C * 8, T) : 4096;
        switch (i) {
            case 0: k_agg<32> <<<aggGrid, T>>>(eS, eD, eC, H, XB); break;
            case 1: k_agg<64> <<<aggGrid, T>>>(eS, eD, eC, H, XB); break;
            case 2: k_agg<128><<<aggGrid, T>>>(eS, eD, eC, H, XB); break;
            case 3: k_agg<128><<<aggGrid, T>>>(eS, eD, eC, H, XB); break;
        }
        // 3. finalize (dinv + bias + relu) + score + key
        switch (i) {
            case 0: k_score<32> <<<gdiv(M * 32, T), T>>>(XB, deg, bb[0], pp[0], M, score, key); break;
            case 1: k_score<64> <<<gdiv(M * 32, T), T>>>(XB, deg, bb[1], pp[1], M, score, key); break;
            case 2: k_score<128><<<gdiv(M * 32, T), T>>>(XB, deg, bb[2], pp[2], M, score, key); break;
            case 3: k_score<128><<<gdiv(M * 32, T), T>>>(XB, deg, bb[3], pp[3], M, score, key); break;
        }
        // 4. radix select (single kernel, in-smem) + zero counters/next deg/next ecnt
        int MN = (i < 3) ? BGR * k : 0;
        k_select<<<BGR, 1024>>>(key, n, k, thresh, allow, cntK, cntE, deg, MN, eCn);
        // 5. compact + gather (lane per node, warp-uniform aggregated atomics)
        switch (i) {
            case 0: k_cg<32> <<<gdiv(M, T), T>>>(key, score, XB, M, n, k, thresh, allow,
                                                 cntK, cntE, remap, pinv + 0, XA); break;
            case 1: k_cg<64> <<<gdiv(M, T), T>>>(key, score, XB, M, n, k, thresh, allow,
                                                 cntK, cntE, remap, pinv + 1, XA); break;
            case 2: k_cg<128><<<gdiv(M, T), T>>>(key, score, XB, M, n, k, thresh, allow,
                                                 cntK, cntE, remap, pinv + 2, XA); break;
            case 3: k_cg<128><<<gdiv(M, T), T>>>(key, score, XB, M, n, k, thresh, allow,
                                                 cntK, cntE, remap, pinv + 3, XA); break;
        }
        // 6. edge remap + next-layer degree (warp-aggregated count atomic)
        if (i < 3) {
            int erGrid = (i == 0) ? gdiv(E0C, T) : 2048;
            k_eremap<<<erGrid, T>>>(eS, eD, eC, remap, eSn, eDn, eCn, deg);
        }
    }

    // readout
    k_read1<<<BGR * 8, 128>>>(XA, pmax, psum, KK[3]);
    k_read2<<<BGR, 128>>>(pmax, psum, meta, cw, cb, fcw, fcb, fc2w, fc2b, out, KK[3]);
    (void)in_sizes; (void)n_in; (void)out_size;
}

// round 7
// speedup vs baseline: 2.1955x; 1.0267x over previous
#include <cuda_runtime.h>
#include <math.h>

// ---------------- static problem constants ----------------
#define BGR 4
#define NN  40962
#define DEG 6
#define E0C (BGR * NN * DEG)          // 983052
#define M0  (BGR * NN)                // 163848

static const int NIN[4] = {40962, 20481, 10241, 5121};   // nodes/graph entering layer i
static const int KK [4] = {20481, 10241,  5121, 2561};   // kept/graph after pool i

// ---------------- device scratch (static, no allocation) ----------------
__device__ __align__(128) float    g_H  [5243392];
__device__ __align__(128) float    g_XB [5243392];
__device__ __align__(128) float    g_XA [2621952];
__device__ float    g_deg[M0];
__device__ float    g_score[M0];
__device__ unsigned g_key[M0];
__device__ int      g_remap[M0];
__device__ int      g_srcbuf[2 * E0C];
__device__ int      g_dstbuf[2 * E0C];
__device__ int      g_ecnt[2];
__device__ int      g_E0cnt = E0C;
__device__ unsigned g_hist12[BGR * 4096];
__device__ unsigned g_thresh[BGR];
__device__ int      g_allow[BGR];
__device__ int      g_cntKeep[BGR];
__device__ int      g_cntEq[BGR];
__device__ float    g_pinv[4];
__device__ float    g_pmax[32 * 128];
__device__ float    g_psum[32 * 128];

// ---------------- helpers ----------------
__device__ __forceinline__ unsigned long long pack2(float a, float b) {
    unsigned long long r;
    asm("mov.b64 %0,{%1,%2};" : "=l"(r) : "f"(a), "f"(b));
    return r;
}
__device__ __forceinline__ void unpack2(unsigned long long v, float& a, float& b) {
    asm("mov.b64 {%0,%1},%2;" : "=f"(a), "=f"(b) : "l"(v));
}
__device__ __forceinline__ void ffma2(unsigned long long& acc, unsigned long long x,
                                      unsigned long long w) {
    asm("fma.rn.f32x2 %0,%1,%2,%0;" : "+l"(acc) : "l"(x), "l"(w));
}
__device__ __forceinline__ void red4(float* p, float4 v) {
    asm volatile("red.global.add.v4.f32 [%0],{%1,%2,%3,%4};"
                 :: "l"(p), "f"(v.x), "f"(v.y), "f"(v.z), "f"(v.w) : "memory");
}

// ---------------- kernels ----------------
// prep: zero layer-0 deg + hist12, compute pinv[4] = 1/||p_i||
__global__ void k_prep(const float* __restrict__ p1, const float* __restrict__ p2,
                       const float* __restrict__ p3, const float* __restrict__ p4,
                       float* __restrict__ pinv, float* __restrict__ deg,
                       unsigned* __restrict__ hist12) {
    int gt = blockIdx.x * blockDim.x + threadIdx.x;
    int gs = gridDim.x * blockDim.x;
    for (int i = gt; i < M0; i += gs) deg[i] = 0.f;
    for (int i = gt; i < BGR * 4096; i += gs) hist12[i] = 0u;
    if (blockIdx.x < 4 && threadIdx.x < 32) {
        const float* p = (blockIdx.x == 0) ? p1 : (blockIdx.x == 1) ? p2
                         : (blockIdx.x == 2) ? p3 : p4;
        int len = (blockIdx.x == 0) ? 32 : (blockIdx.x == 1) ? 64 : 128;
        float acc = 0.f;
        for (int f = threadIdx.x; f < len; f += 32) { float v = p[f]; acc += v * v; }
#pragma unroll
        for (int o = 16; o; o >>= 1) acc += __shfl_down_sync(0xffffffffu, acc, o);
        if (threadIdx.x == 0) pinv[blockIdx.x] = rsqrtf(acc);
    }
}

__global__ void k_deg0(const int* __restrict__ dst, float* __restrict__ deg) {
    int e = blockIdx.x * blockDim.x + threadIdx.x;
    if (e < E0C) atomicAdd(&deg[dst[e]], 1.0f);
}

// smem-tiled matmul: H = XB = (X@W) * dinv[m]   (norm pre-scaled into H')
template <int FI, int FO>
__global__ void k_mm(const float* __restrict__ X, const float* __restrict__ W,
                     const float* __restrict__ deg, float* __restrict__ H,
                     float* __restrict__ XB, int M) {
    constexpr int J = FO / 4;       // threads per row
    constexpr int G = 256 / J;      // rows per block
    __shared__ float sX[G * FI];
    int r0 = blockIdx.x * G;
    for (int idx = threadIdx.x; idx < G * FI; idx += 256) {
        int r = r0 + idx / FI;
        sX[idx] = (r < M) ? X[(size_t)r * FI + (idx % FI)] : 0.f;
    }
    __syncthreads();
    int g = threadIdx.x / J, j = (threadIdx.x % J) * 4;
    int m = r0 + g;
    if (m >= M) return;
    const float* xr = sX + g * FI;
    unsigned long long acc0 = 0ull, acc1 = 0ull;
#pragma unroll
    for (int kq = 0; kq < FI; kq++) {
        float xv = xr[kq];
        unsigned long long xx = pack2(xv, xv);
        ulonglong2 wv = *(const ulonglong2*)(W + kq * FO + j);
        ffma2(acc0, xx, wv.x);
        ffma2(acc1, xx, wv.y);
    }
    float a0, a1, a2, a3;
    unpack2(acc0, a0, a1);
    unpack2(acc1, a2, a3);
    float dv = rsqrtf(deg[m] + 1.0f);
    float4 hv = make_float4(a0 * dv, a1 * dv, a2 * dv, a3 * dv);
    *(float4*)(H + (size_t)m * FO + j) = hv;
    *(float4*)(XB + (size_t)m * FO + j) = hv;
}

// edge aggregation: XB[d] += H'[s], thread per (edge, 4-feature chunk), v4 RED
template <int FO>
__global__ void k_agg(const int* __restrict__ src, const int* __restrict__ dst,
                      const int* __restrict__ ecnt, const float* __restrict__ H,
                      float* __restrict__ XB) {
    constexpr int LC = (FO == 32) ? 3 : (FO == 64) ? 4 : 5;   // log2(FO/4)
    constexpr int CM = (1 << LC) - 1;
    int total = (*ecnt) << LC;
    int t = blockIdx.x * blockDim.x + threadIdx.x;
    int stride = gridDim.x * blockDim.x;
    for (int i = t; i < total; i += stride) {
        int e = i >> LC, c = i & CM;
        int s = src[e], d = dst[e];
        float4 h = *(const float4*)(H + (size_t)s * FO + c * 4);
        red4(XB + (size_t)d * FO + c * 4, h);
    }
}

// fused finalize-in-registers: v = relu(XB*dinv + b), score, key, 12-bit histogram.
// Does NOT write XB back (cg re-applies the finalize on the kept rows).
template <int FO>
__global__ void k_score(const float* __restrict__ XB, const float* __restrict__ deg,
                        const float* __restrict__ bias, const float* __restrict__ p,
                        int M, int n, float* __restrict__ score,
                        unsigned* __restrict__ key, unsigned* __restrict__ hist12) {
    int m = (blockIdx.x * blockDim.x + threadIdx.x) >> 5;
    int lane = threadIdx.x & 31;
    if (m >= M) return;
    float dv = rsqrtf(deg[m] + 1.0f);
    float acc = 0.f;
#pragma unroll
    for (int f = lane; f < FO; f += 32) {
        float v = XB[(size_t)m * FO + f] * dv + bias[f];
        acc += fmaxf(v, 0.f) * p[f];
    }
#pragma unroll
    for (int o = 16; o; o >>= 1) acc += __shfl_down_sync(0xffffffffu, acc, o);
    if (lane == 0) {
        score[m] = acc;
        unsigned u = __float_as_uint(acc);
        unsigned kk = (u & 0x80000000u) ? ~u : (u | 0x80000000u);
        key[m] = kk;
        atomicAdd(&hist12[(m / n) * 4096 + (kk >> 20)], 1u);
    }
}

// 3-stage select: phase 1 reads precomputed 12-bit bins (then re-zeros them),
// phase 2 scans keys histogramming bits[19:8], phase 3 scans final byte.
// Also zeroes counters, next-layer deg, next-layer edge count.
__global__ void __launch_bounds__(1024)
k_select(const unsigned* __restrict__ key, int n, int k,
         unsigned* __restrict__ hist12, unsigned* __restrict__ thresh,
         int* __restrict__ allow, int* __restrict__ cntK, int* __restrict__ cntE,
         float* __restrict__ degN, int MN, int* __restrict__ eCn) {
    __shared__ unsigned sh[4096];
    __shared__ unsigned arr[1024];
    __shared__ unsigned sPfx;
    __shared__ int sW;
    int b = blockIdx.x, t = threadIdx.x;
    const unsigned* kb = key + b * n;
    unsigned* hb = hist12 + b * 4096;

    // ---- phase 1: top 12 bits (bins precomputed by k_score) ----
    for (int i = t; i < 4096; i += 1024) { sh[i] = hb[i]; hb[i] = 0u; }
    __syncthreads();
    {
        unsigned s = sh[t * 4] + sh[t * 4 + 1] + sh[t * 4 + 2] + sh[t * 4 + 3];
        arr[t] = s;
        __syncthreads();
        for (int off = 1; off < 1024; off <<= 1) {
            unsigned v = (t + off < 1024) ? arr[t + off] : 0u;
            __syncthreads();
            arr[t] += v;
            __syncthreads();
        }
        unsigned above = arr[t] - s;
        if (above < (unsigned)k && above + s >= (unsigned)k) {
            unsigned cum = above;
            for (int j = 3; j >= 0; j--) {
                unsigned h = sh[t * 4 + j];
                if (cum + h >= (unsigned)k) { sPfx = t * 4 + j; sW = k - (int)cum; break; }
                cum += h;
            }
        }
    }
    __syncthreads();
    unsigned pfx1 = sPfx;
    int want = sW;

    // ---- phase 2: bits [19:8] among keys matching pfx1 ----
    __syncthreads();
    for (int i = t; i < 4096; i += 1024) sh[i] = 0u;
    __syncthreads();
    for (int i = t; i < n; i += 1024) {
        unsigned kk = kb[i];
        if ((kk >> 20) == pfx1) atomicAdd(&sh[(kk >> 8) & 0xFFFu], 1u);
    }
    __syncthreads();
    {
        unsigned s = sh[t * 4] + sh[t * 4 + 1] + sh[t * 4 + 2] + sh[t * 4 + 3];
        arr[t] = s;
        __syncthreads();
        for (int off = 1; off < 1024; off <<= 1) {
            unsigned v = (t + off < 1024) ? arr[t + off] : 0u;
            __syncthreads();
            arr[t] += v;
            __syncthreads();
        }
        unsigned above = arr[t] - s;
        if (above < (unsigned)want && above + s >= (unsigned)want) {
            unsigned cum = above;
            for (int j = 3; j >= 0; j--) {
                unsigned h = sh[t * 4 + j];
                if (cum + h >= (unsigned)want) { sPfx = t * 4 + j; sW = want - (int)cum; break; }
                cum += h;
            }
        }
    }
    __syncthreads();
    unsigned pfx2 = sPfx;
    want = sW;
    unsigned pfx24 = (pfx1 << 12) | pfx2;

    // ---- phase 3: final byte among keys matching pfx24 ----
    __syncthreads();
    if (t < 256) sh[t] = 0u;
    __syncthreads();
    for (int i = t; i < n; i += 1024) {
        unsigned kk = kb[i];
        if ((kk >> 8) == pfx24) atomicAdd(&sh[kk & 0xFFu], 1u);
    }
    __syncthreads();
    if (t == 0) {
        unsigned cum = 0;
        int d = 255;
        for (;;) {
            unsigned h = sh[d];
            if (cum + h >= (unsigned)want || d == 0) break;
            cum += h;
            d--;
        }
        thresh[b] = (pfx24 << 8) | (unsigned)d;
        allow[b] = want - (int)cum;
        cntK[b] = 0;
        cntE[b] = 0;
        if (b == 0) *eCn = 0;
    }
    for (int i = b * 1024 + t; i < MN; i += 4096) degN[i] = 0.f;
}

// fused compact + gather: lane per node; warp-uniform collectives; applies the
// finalize (dinv + bias + relu) and tanh scale on kept rows; packs multiple
// rows per copy iteration (FO=32: 4 rows, FO=64: 2 rows).
template <int FO>
__global__ void k_cg(const unsigned* __restrict__ key, const float* __restrict__ score,
                     const float* __restrict__ XB, const float* __restrict__ deg,
                     const float* __restrict__ bias, int M, int n, int k,
                     const unsigned* __restrict__ thresh, const int* __restrict__ allow,
                     int* __restrict__ cntK, int* __restrict__ cntE,
                     int* __restrict__ remap, const float* __restrict__ pinv,
                     float* __restrict__ XA) {
    int lane = threadIdx.x & 31;
    int base = ((blockIdx.x * blockDim.x + threadIdx.x) >> 5) << 5;  // first node of warp
    if (base >= M) return;                                           // warp-uniform
    int m = base + lane;
    bool active = (m < M);
    float pv = *pinv;

    int b = 0;
    bool keep = false;
    if (active) {
        b = m / n;
        unsigned kk = key[m], t = thresh[b];
        keep = kk > t;
        if (!keep && kk == t)                               // rare tie path
            keep = (atomicAdd(&cntE[b], 1) < allow[b]);
    }

    int nid = -1;
    bool uniformWarp = (base + 31 < M) && ((base / n) == ((base + 31) / n));
    if (uniformWarp) {
        unsigned keepmask = __ballot_sync(0xffffffffu, keep);
        int leader = __ffs(keepmask) - 1;
        int basepos = 0;
        if (keep && lane == leader)
            basepos = atomicAdd(&cntK[b], __popc(keepmask));
        basepos = __shfl_sync(0xffffffffu, basepos, (leader < 0) ? 0 : leader);
        if (keep)
            nid = b * k + basepos + __popc(keepmask & ((1u << lane) - 1u));
    } else {
        if (keep) nid = b * k + atomicAdd(&cntK[b], 1);
    }
    if (active) remap[m] = nid;

    float dvm = active ? rsqrtf(deg[m] + 1.0f) : 0.f;
    float tv = keep ? tanhf(score[m] * pv) : 0.f;

    constexpr int LPR = FO / 4;   // lanes per row (8 / 16 / 32)
    constexpr int RPI = 32 / LPR; // rows per iteration (4 / 2 / 1)
    int sub = lane / LPR;
    int chunk = lane % LPR;
    float4 bv = *(const float4*)(bias + chunk * 4);

    unsigned fullkeep = __ballot_sync(0xffffffffu, keep);
    int count = __popc(fullkeep);
#pragma unroll 1
    for (int g = 0; g < count; g += RPI) {
        int slot = g + sub;
        int r = (slot < count) ? (int)__fns(fullkeep, 0, slot + 1) : 0;
        int nid_r = __shfl_sync(0xffffffffu, nid, r);
        float t_r  = __shfl_sync(0xffffffffu, tv, r);
        float dv_r = __shfl_sync(0xffffffffu, dvm, r);
        if (slot < count) {
            int m_r = base + r;
            float4 v = *(const float4*)(XB + (size_t)m_r * FO + chunk * 4);
            v.x = fmaxf(v.x * dv_r + bv.x, 0.f) * t_r;
            v.y = fmaxf(v.y * dv_r + bv.y, 0.f) * t_r;
            v.z = fmaxf(v.z * dv_r + bv.z, 0.f) * t_r;
            v.w = fmaxf(v.w * dv_r + bv.w, 0.f) * t_r;
            *(float4*)(XA + (size_t)nid_r * FO + chunk * 4) = v;
        }
    }
}

// edge remap/compact + next-layer degree; warp-aggregated ecntN atomic
__global__ void k_eremap(const int* __restrict__ srcO, const int* __restrict__ dstO,
                         const int* __restrict__ ecntO, const int* __restrict__ remap,
                         int* __restrict__ srcN, int* __restrict__ dstN,
                         int* __restrict__ ecntN, float* __restrict__ degN) {
    int E = *ecntO;
    int gt = blockIdx.x * blockDim.x + threadIdx.x;
    int lane = threadIdx.x & 31;
    int stride = gridDim.x * blockDim.x;
    for (int e = gt; __any_sync(0xffffffffu, e < E); e += stride) {
        bool in = (e < E);
        int s = -1, d = -1;
        if (in) {
            s = remap[srcO[e]];
            d = remap[dstO[e]];
        }
        bool valid = in && (s >= 0) && (d >= 0);
        unsigned mask = __ballot_sync(0xffffffffu, valid);
        if (!mask) continue;
        int leader = __ffs(mask) - 1;
        int basepos = 0;
        if (lane == leader) basepos = atomicAdd(ecntN, __popc(mask));
        basepos = __shfl_sync(0xffffffffu, basepos, leader);
        if (valid) {
            int pos = basepos + __popc(mask & ((1u << lane) - 1u));
            srcN[pos] = s;
            dstN[pos] = d;
            atomicAdd(&degN[d], 1.f);
        }
    }
}

// readout part 1: partial max/sum over row slices (8 slices per graph)
__global__ void k_read1(const float* __restrict__ X, float* __restrict__ pmax,
                        float* __restrict__ psum, int kn) {
    int b = blockIdx.x >> 3, s = blockIdx.x & 7, f = threadIdx.x;   // 128 threads
    int per = (kn + 7) / 8;
    int i0 = s * per, i1 = min(kn, i0 + per);
    float mx = -3.4e38f, sm = 0.f;
    const float* base = X + (size_t)b * kn * 128 + f;
    for (int i = i0; i < i1; i++) {
        float v = base[(size_t)i * 128];
        mx = fmaxf(mx, v);
        sm += v;
    }
    pmax[blockIdx.x * 128 + f] = mx;
    psum[blockIdx.x * 128 + f] = sm;
}

// readout part 2: final reduce + metadata conv + fc + fc2
__global__ void k_read2(const float* __restrict__ pmax, const float* __restrict__ psum,
                        const float* __restrict__ meta, const float* __restrict__ cw,
                        const float* __restrict__ cb, const float* __restrict__ fcw,
                        const float* __restrict__ fcb, const float* __restrict__ fc2w,
                        const float* __restrict__ fc2b, float* __restrict__ out, int kn) {
    __shared__ float v[260];
    __shared__ float red[128];
    int b = blockIdx.x, f = threadIdx.x;   // 128 threads
    float mx = -3.4e38f, sm = 0.f;
#pragma unroll
    for (int s = 0; s < 8; s++) {
        mx = fmaxf(mx, pmax[(b * 8 + s) * 128 + f]);
        sm += psum[(b * 8 + s) * 128 + f];
    }
    v[f] = mx;
    v[128 + f] = sm / (float)kn;
    if (f < 4) {
        float mv = meta[b] * cw[f] + cb[f];
        v[256 + f] = mv > 0.f ? mv : 0.f;
    }
    __syncthreads();
    float acc = fcb[f];
    for (int i = 0; i < 260; i++) acc += v[i] * fcw[i * 128 + f];
    float hv = acc > 0.f ? acc : 0.f;
    red[f] = hv * fc2w[f];
    __syncthreads();
    for (int s = 64; s > 0; s >>= 1) {
        if (f < s) red[f] += red[f + s];
        __syncthreads();
    }
    if (f == 0) out[b] = red[0] + fc2b[0];
}

// ---------------- host orchestration ----------------
static inline int gdiv(int n, int t) { return (n + t - 1) / t; }

extern "C" void kernel_launch(void* const* d_in, const int* in_sizes, int n_in,
                              void* d_out, int out_size) {
    const float* x0   = (const float*)d_in[0];
    const int*   ei   = (const int*)  d_in[1];
    const float* meta = (const float*)d_in[2];
    const float* W[4]  = {(const float*)d_in[3], (const float*)d_in[6],
                          (const float*)d_in[9], (const float*)d_in[12]};
    const float* bb[4] = {(const float*)d_in[4], (const float*)d_in[7],
                          (const float*)d_in[10], (const float*)d_in[13]};
    const float* pp[4] = {(const float*)d_in[5], (const float*)d_in[8],
                          (const float*)d_in[11], (const float*)d_in[14]};
    const float* cw   = (const float*)d_in[15];
    const float* cb   = (const float*)d_in[16];
    const float* fcw  = (const float*)d_in[17];
    const float* fcb  = (const float*)d_in[18];
    const float* fc2w = (const float*)d_in[19];
    const float* fc2b = (const float*)d_in[20];
    float* out = (float*)d_out;

    float *H, *XB, *XA, *deg, *score, *pinv, *pmax, *psum;
    unsigned *key, *thresh, *hist12;
    int *remap, *allow, *cntK, *cntE, *srcb, *dstb, *ecnt, *e0c;
    cudaGetSymbolAddress((void**)&H, g_H);
    cudaGetSymbolAddress((void**)&XB, g_XB);
    cudaGetSymbolAddress((void**)&XA, g_XA);
    cudaGetSymbolAddress((void**)&deg, g_deg);
    cudaGetSymbolAddress((void**)&score, g_score);
    cudaGetSymbolAddress((void**)&key, g_key);
    cudaGetSymbolAddress((void**)&remap, g_remap);
    cudaGetSymbolAddress((void**)&srcb, g_srcbuf);
    cudaGetSymbolAddress((void**)&dstb, g_dstbuf);
    cudaGetSymbolAddress((void**)&ecnt, g_ecnt);
    cudaGetSymbolAddress((void**)&e0c, g_E0cnt);
    cudaGetSymbolAddress((void**)&hist12, g_hist12);
    cudaGetSymbolAddress((void**)&thresh, g_thresh);
    cudaGetSymbolAddress((void**)&allow, g_allow);
    cudaGetSymbolAddress((void**)&cntK, g_cntKeep);
    cudaGetSymbolAddress((void**)&cntE, g_cntEq);
    cudaGetSymbolAddress((void**)&pinv, g_pinv);
    cudaGetSymbolAddress((void**)&pmax, g_pmax);
    cudaGetSymbolAddress((void**)&psum, g_psum);

    const int T = 256;

    k_prep<<<256, T>>>(pp[0], pp[1], pp[2], pp[3], pinv, deg, hist12);
    k_deg0<<<gdiv(E0C, T), T>>>(ei + E0C, deg);

    for (int i = 0; i < 4; i++) {
        int n = NIN[i], M = BGR * n, k = KK[i];
        const float* Xin = i ? XA : x0;
        const int* eS = i ? (srcb + ((i + 1) & 1) * E0C) : ei;
        const int* eD = i ? (dstb + ((i + 1) & 1) * E0C) : (ei + E0C);
        const int* eC = i ? (ecnt + ((i + 1) & 1)) : e0c;
        int* eSn = srcb + (i & 1) * E0C;
        int* eDn = dstb + (i & 1) * E0C;
        int* eCn = ecnt + (i & 1);

        // 1. H' = XB = (X@W)*dinv (smem-tiled)
        switch (i) {
            case 0: k_mm<4, 32>   <<<gdiv(M, 32), T>>>(Xin, W[0], deg, H, XB, M); break;
            case 1: k_mm<32, 64>  <<<gdiv(M, 16), T>>>(Xin, W[1], deg, H, XB, M); break;
            case 2: k_mm<64, 128> <<<gdiv(M, 8),  T>>>(Xin, W[2], deg, H, XB, M); break;
            case 3: k_mm<128, 128><<<gdiv(M, 8),  T>>>(Xin, W[3], deg, H, XB, M); break;
        }
        // 2. aggregate: XB[d] += H'[s] (v4 vector RED)
        int aggGrid = (i == 0) ? gdiv(E0C * 8, T) : 4096;
        switch (i) {
            case 0: k_agg<32> <<<aggGrid, T>>>(eS, eD, eC, H, XB); break;
            case 1: k_agg<64> <<<aggGrid, T>>>(eS, eD, eC, H, XB); break;
            case 2: k_agg<128><<<aggGrid, T>>>(eS, eD, eC, H, XB); break;
            case 3: k_agg<128><<<aggGrid, T>>>(eS, eD, eC, H, XB); break;
        }
        // 3. score + key + fused 12-bit histogram (no XB writeback)
        switch (i) {
            case 0: k_score<32> <<<gdiv(M * 32, T), T>>>(XB, deg, bb[0], pp[0], M, n, score, key, hist12); break;
            case 1: k_score<64> <<<gdiv(M * 32, T), T>>>(XB, deg, bb[1], pp[1], M, n, score, key, hist12); break;
            case 2: k_score<128><<<gdiv(M * 32, T), T>>>(XB, deg, bb[2], pp[2], M, n, score, key, hist12); break;
            case 3: k_score<128><<<gdiv(M * 32, T), T>>>(XB, deg, bb[3], pp[3], M, n, score, key, hist12); break;
        }
        // 4. 3-stage select (2 key scans) + zero counters/next deg/next ecnt
        int MN = (i < 3) ? BGR * k : 0;
        k_select<<<BGR, 1024>>>(key, n, k, hist12, thresh, allow, cntK, cntE, deg, MN, eCn);
        // 5. compact + gather (finalize applied on kept rows)
        switch (i) {
            case 0: k_cg<32> <<<gdiv(M, T), T>>>(key, score, XB, deg, bb[0], M, n, k, thresh,
                                                 allow, cntK, cntE, remap, pinv + 0, XA); break;
            case 1: k_cg<64> <<<gdiv(M, T), T>>>(key, score, XB, deg, bb[1], M, n, k, thresh,
                                                 allow, cntK, cntE, remap, pinv + 1, XA); break;
            case 2: k_cg<128><<<gdiv(M, T), T>>>(key, score, XB, deg, bb[2], M, n, k, thresh,
                                                 allow, cntK, cntE, remap, pinv + 2, XA); break;
            case 3: k_cg<128><<<gdiv(M, T), T>>>(key, score, XB, deg, bb[3], M, n, k, thresh,
                                                 allow, cntK, cntE, remap, pinv + 3, XA); break;
        }
        // 6. edge remap + next-layer degree (warp-aggregated count atomic)
        if (i < 3) {
            int erGrid = (i == 0) ? gdiv(E0C, T) : 2048;
            k_eremap<<<erGrid, T>>>(eS, eD, eC, remap, eSn, eDn, eCn, deg);
        }
    }

    // readout
    k_read1<<<BGR * 8, 128>>>(XA, pmax, psum, KK[3]);
    k_read2<<<BGR, 128>>>(pmax, psum, meta, cw, cb, fcw, fcb, fc2w, fc2b, out, KK[3]);
    (void)in_sizes; (void)n_in; (void)out_size;
}

// round 11
// speedup vs baseline: 2.2287x; 1.0151x over previous
#include <cuda_runtime.h>
#include <math.h>

// ---------------- static problem constants ----------------
#define BGR 4
#define NN  40962
#define DEG 6
#define E0C (BGR * NN * DEG)          // 983052
#define M0  (BGR * NN)                // 163848

static const int NIN[4] = {40962, 20481, 10241, 5121};   // nodes/graph entering layer i
static const int KK [4] = {20481, 10241,  5121, 2561};   // kept/graph after pool i

// ---------------- device scratch (static, no allocation) ----------------
__device__ __align__(128) float    g_H  [5243392];
__device__ __align__(128) float    g_XB [5243392];
__device__ __align__(128) float    g_XA [2621952];
__device__ float    g_deg[M0];
__device__ float    g_score[M0];
__device__ unsigned g_key[M0];
__device__ int      g_remap[M0];
__device__ int      g_srcbuf[2 * E0C];
__device__ int      g_dstbuf[2 * E0C];
__device__ int      g_ecnt[2];
__device__ int      g_E0cnt = E0C;
__device__ unsigned g_hist12[BGR * 4096];
__device__ unsigned g_thresh[BGR];
__device__ int      g_allow[BGR];
__device__ int      g_cntKeep[BGR];
__device__ int      g_cntEq[BGR];
__device__ float    g_pinv[4];
__device__ float    g_pmax[32 * 128];
__device__ float    g_psum[32 * 128];

// ---------------- helpers ----------------
__device__ __forceinline__ unsigned long long pack2(float a, float b) {
    unsigned long long r;
    asm("mov.b64 %0,{%1,%2};" : "=l"(r) : "f"(a), "f"(b));
    return r;
}
__device__ __forceinline__ void unpack2(unsigned long long v, float& a, float& b) {
    asm("mov.b64 {%0,%1},%2;" : "=f"(a), "=f"(b) : "l"(v));
}
__device__ __forceinline__ void ffma2(unsigned long long& acc, unsigned long long x,
                                      unsigned long long w) {
    asm("fma.rn.f32x2 %0,%1,%2,%0;" : "+l"(acc) : "l"(x), "l"(w));
}
__device__ __forceinline__ void red4(float* p, float4 v) {
    asm volatile("red.global.add.v4.f32 [%0],{%1,%2,%3,%4};"
                 :: "l"(p), "f"(v.x), "f"(v.y), "f"(v.z), "f"(v.w) : "memory");
}
// wait for the programmatic-dependency producer before touching its data
__device__ __forceinline__ void gdep() { cudaGridDependencySynchronize(); }

// ---------------- kernels ----------------
// prep: zero layer-0 deg + hist12, compute pinv[4] = 1/||p_i||
__global__ void k_prep(const float* __restrict__ p1, const float* __restrict__ p2,
                       const float* __restrict__ p3, const float* __restrict__ p4,
                       float* __restrict__ pinv, float* __restrict__ deg,
                       unsigned* __restrict__ hist12) {
    gdep();
    int gt = blockIdx.x * blockDim.x + threadIdx.x;
    int gs = gridDim.x * blockDim.x;
    for (int i = gt; i < M0; i += gs) deg[i] = 0.f;
    for (int i = gt; i < BGR * 4096; i += gs) hist12[i] = 0u;
    if (blockIdx.x < 4 && threadIdx.x < 32) {
        const float* p = (blockIdx.x == 0) ? p1 : (blockIdx.x == 1) ? p2
                         : (blockIdx.x == 2) ? p3 : p4;
        int len = (blockIdx.x == 0) ? 32 : (blockIdx.x == 1) ? 64 : 128;
        float acc = 0.f;
        for (int f = threadIdx.x; f < len; f += 32) { float v = p[f]; acc += v * v; }
#pragma unroll
        for (int o = 16; o; o >>= 1) acc += __shfl_down_sync(0xffffffffu, acc, o);
        if (threadIdx.x == 0) pinv[blockIdx.x] = rsqrtf(acc);
    }
}

__global__ void k_deg0(const int* __restrict__ dst, float* __restrict__ deg) {
    gdep();
    int e = blockIdx.x * blockDim.x + threadIdx.x;
    if (e < E0C) atomicAdd(&deg[dst[e]], 1.0f);
}

// smem-tiled matmul: H = XB = (X@W) * dinv[m]   (norm pre-scaled into H')
template <int FI, int FO>
__global__ void k_mm(const float* __restrict__ X, const float* __restrict__ W,
                     const float* __restrict__ deg, float* __restrict__ H,
                     float* __restrict__ XB, int M) {
    gdep();
    constexpr int J = FO / 4;       // threads per row
    constexpr int G = 256 / J;      // rows per block
    __shared__ float sX[G * FI];
    int r0 = blockIdx.x * G;
    for (int idx = threadIdx.x; idx < G * FI; idx += 256) {
        int r = r0 + idx / FI;
        sX[idx] = (r < M) ? X[(size_t)r * FI + (idx % FI)] : 0.f;
    }
    __syncthreads();
    int g = threadIdx.x / J, j = (threadIdx.x % J) * 4;
    int m = r0 + g;
    if (m >= M) return;
    const float* xr = sX + g * FI;
    unsigned long long acc0 = 0ull, acc1 = 0ull;
#pragma unroll
    for (int kq = 0; kq < FI; kq++) {
        float xv = xr[kq];
        unsigned long long xx = pack2(xv, xv);
        ulonglong2 wv = *(const ulonglong2*)(W + kq * FO + j);
        ffma2(acc0, xx, wv.x);
        ffma2(acc1, xx, wv.y);
    }
    float a0, a1, a2, a3;
    unpack2(acc0, a0, a1);
    unpack2(acc1, a2, a3);
    float dv = rsqrtf(deg[m] + 1.0f);
    float4 hv = make_float4(a0 * dv, a1 * dv, a2 * dv, a3 * dv);
    *(float4*)(H + (size_t)m * FO + j) = hv;
    *(float4*)(XB + (size_t)m * FO + j) = hv;
}

// edge aggregation: XB[d] += H'[s], thread per (edge, 4-feature chunk), v4 RED
template <int FO>
__global__ void k_agg(const int* __restrict__ src, const int* __restrict__ dst,
                      const int* __restrict__ ecnt, const float* __restrict__ H,
                      float* __restrict__ XB) {
    gdep();
    constexpr int LC = (FO == 32) ? 3 : (FO == 64) ? 4 : 5;   // log2(FO/4)
    constexpr int CM = (1 << LC) - 1;
    int total = (*ecnt) << LC;
    int t = blockIdx.x * blockDim.x + threadIdx.x;
    int stride = gridDim.x * blockDim.x;
    for (int i = t; i < total; i += stride) {
        int e = i >> LC, c = i & CM;
        int s = src[e], d = dst[e];
        float4 h = *(const float4*)(H + (size_t)s * FO + c * 4);
        red4(XB + (size_t)d * FO + c * 4, h);
    }
}

// fused finalize-in-registers: v = relu(XB*dinv + b), score, key, 12-bit histogram.
// Does NOT write XB back (cg re-applies the finalize on the kept rows).
template <int FO>
__global__ void k_score(const float* __restrict__ XB, const float* __restrict__ deg,
                        const float* __restrict__ bias, const float* __restrict__ p,
                        int M, int n, float* __restrict__ score,
                        unsigned* __restrict__ key, unsigned* __restrict__ hist12) {
    gdep();
    int m = (blockIdx.x * blockDim.x + threadIdx.x) >> 5;
    int lane = threadIdx.x & 31;
    if (m >= M) return;
    float dv = rsqrtf(deg[m] + 1.0f);
    float acc = 0.f;
#pragma unroll
    for (int f = lane; f < FO; f += 32) {
        float v = XB[(size_t)m * FO + f] * dv + bias[f];
        acc += fmaxf(v, 0.f) * p[f];
    }
#pragma unroll
    for (int o = 16; o; o >>= 1) acc += __shfl_down_sync(0xffffffffu, acc, o);
    if (lane == 0) {
        score[m] = acc;
        unsigned u = __float_as_uint(acc);
        unsigned kk = (u & 0x80000000u) ? ~u : (u | 0x80000000u);
        key[m] = kk;
        atomicAdd(&hist12[(m / n) * 4096 + (kk >> 20)], 1u);
    }
}

// 3-stage select: phase 1 reads precomputed 12-bit bins (then re-zeros them),
// phase 2 scans keys histogramming bits[19:8], phase 3 scans final byte.
// Also zeroes counters, next-layer deg, next-layer edge count.
__global__ void __launch_bounds__(1024)
k_select(const unsigned* __restrict__ key, int n, int k,
         unsigned* __restrict__ hist12, unsigned* __restrict__ thresh,
         int* __restrict__ allow, int* __restrict__ cntK, int* __restrict__ cntE,
         float* __restrict__ degN, int MN, int* __restrict__ eCn) {
    gdep();
    __shared__ unsigned sh[4096];
    __shared__ unsigned arr[1024];
    __shared__ unsigned sPfx;
    __shared__ int sW;
    int b = blockIdx.x, t = threadIdx.x;
    const unsigned* kb = key + b * n;
    unsigned* hb = hist12 + b * 4096;

    // ---- phase 1: top 12 bits (bins precomputed by k_score) ----
    for (int i = t; i < 4096; i += 1024) { sh[i] = hb[i]; hb[i] = 0u; }
    __syncthreads();
    {
        unsigned s = sh[t * 4] + sh[t * 4 + 1] + sh[t * 4 + 2] + sh[t * 4 + 3];
        arr[t] = s;
        __syncthreads();
        for (int off = 1; off < 1024; off <<= 1) {
            unsigned v = (t + off < 1024) ? arr[t + off] : 0u;
            __syncthreads();
            arr[t] += v;
            __syncthreads();
        }
        unsigned above = arr[t] - s;
        if (above < (unsigned)k && above + s >= (unsigned)k) {
            unsigned cum = above;
            for (int j = 3; j >= 0; j--) {
                unsigned h = sh[t * 4 + j];
                if (cum + h >= (unsigned)k) { sPfx = t * 4 + j; sW = k - (int)cum; break; }
                cum += h;
            }
        }
    }
    __syncthreads();
    unsigned pfx1 = sPfx;
    int want = sW;

    // ---- phase 2: bits [19:8] among keys matching pfx1 ----
    __syncthreads();
    for (int i = t; i < 4096; i += 1024) sh[i] = 0u;
    __syncthreads();
    for (int i = t; i < n; i += 1024) {
        unsigned kk = kb[i];
        if ((kk >> 20) == pfx1) atomicAdd(&sh[(kk >> 8) & 0xFFFu], 1u);
    }
    __syncthreads();
    {
        unsigned s = sh[t * 4] + sh[t * 4 + 1] + sh[t * 4 + 2] + sh[t * 4 + 3];
        arr[t] = s;
        __syncthreads();
        for (int off = 1; off < 1024; off <<= 1) {
            unsigned v = (t + off < 1024) ? arr[t + off] : 0u;
            __syncthreads();
            arr[t] += v;
            __syncthreads();
        }
        unsigned above = arr[t] - s;
        if (above < (unsigned)want && above + s >= (unsigned)want) {
            unsigned cum = above;
            for (int j = 3; j >= 0; j--) {
                unsigned h = sh[t * 4 + j];
                if (cum + h >= (unsigned)want) { sPfx = t * 4 + j; sW = want - (int)cum; break; }
                cum += h;
            }
        }
    }
    __syncthreads();
    unsigned pfx2 = sPfx;
    want = sW;
    unsigned pfx24 = (pfx1 << 12) | pfx2;

    // ---- phase 3: final byte among keys matching pfx24 ----
    __syncthreads();
    if (t < 256) sh[t] = 0u;
    __syncthreads();
    for (int i = t; i < n; i += 1024) {
        unsigned kk = kb[i];
        if ((kk >> 8) == pfx24) atomicAdd(&sh[kk & 0xFFu], 1u);
    }
    __syncthreads();
    if (t == 0) {
        unsigned cum = 0;
        int d = 255;
        for (;;) {
            unsigned h = sh[d];
            if (cum + h >= (unsigned)want || d == 0) break;
            cum += h;
            d--;
        }
        thresh[b] = (pfx24 << 8) | (unsigned)d;
        allow[b] = want - (int)cum;
        cntK[b] = 0;
        cntE[b] = 0;
        if (b == 0) *eCn = 0;
    }
    for (int i = b * 1024 + t; i < MN; i += 4096) degN[i] = 0.f;
}

// fused compact + gather: lane per node; warp-uniform collectives; applies the
// finalize (dinv + bias + relu) and tanh scale on kept rows; packs multiple
// rows per copy iteration (FO=32: 4 rows, FO=64: 2 rows).
template <int FO>
__global__ void k_cg(const unsigned* __restrict__ key, const float* __restrict__ score,
                     const float* __restrict__ XB, const float* __restrict__ deg,
                     const float* __restrict__ bias, int M, int n, int k,
                     const unsigned* __restrict__ thresh, const int* __restrict__ allow,
                     int* __restrict__ cntK, int* __restrict__ cntE,
                     int* __restrict__ remap, const float* __restrict__ pinv,
                     float* __restrict__ XA) {
    gdep();
    int lane = threadIdx.x & 31;
    int base = ((blockIdx.x * blockDim.x + threadIdx.x) >> 5) << 5;  // first node of warp
    if (base >= M) return;                                           // warp-uniform
    int m = base + lane;
    bool active = (m < M);
    float pv = *pinv;

    int b = 0;
    bool keep = false;
    if (active) {
        b = m / n;
        unsigned kk = key[m], t = thresh[b];
        keep = kk > t;
        if (!keep && kk == t)                               // rare tie path
            keep = (atomicAdd(&cntE[b], 1) < allow[b]);
    }

    int nid = -1;
    bool uniformWarp = (base + 31 < M) && ((base / n) == ((base + 31) / n));
    if (uniformWarp) {
        unsigned keepmask = __ballot_sync(0xffffffffu, keep);
        int leader = __ffs(keepmask) - 1;
        int basepos = 0;
        if (keep && lane == leader)
            basepos = atomicAdd(&cntK[b], __popc(keepmask));
        basepos = __shfl_sync(0xffffffffu, basepos, (leader < 0) ? 0 : leader);
        if (keep)
            nid = b * k + basepos + __popc(keepmask & ((1u << lane) - 1u));
    } else {
        if (keep) nid = b * k + atomicAdd(&cntK[b], 1);
    }
    if (active) remap[m] = nid;

    float dvm = active ? rsqrtf(deg[m] + 1.0f) : 0.f;
    float tv = keep ? tanhf(score[m] * pv) : 0.f;

    constexpr int LPR = FO / 4;   // lanes per row (8 / 16 / 32)
    constexpr int RPI = 32 / LPR; // rows per iteration (4 / 2 / 1)
    int sub = lane / LPR;
    int chunk = lane % LPR;
    float4 bv = *(const float4*)(bias + chunk * 4);

    unsigned fullkeep = __ballot_sync(0xffffffffu, keep);
    int count = __popc(fullkeep);
#pragma unroll 1
    for (int g = 0; g < count; g += RPI) {
        int slot = g + sub;
        int r = (slot < count) ? (int)__fns(fullkeep, 0, slot + 1) : 0;
        int nid_r = __shfl_sync(0xffffffffu, nid, r);
        float t_r  = __shfl_sync(0xffffffffu, tv, r);
        float dv_r = __shfl_sync(0xffffffffu, dvm, r);
        if (slot < count) {
            int m_r = base + r;
            float4 v = *(const float4*)(XB + (size_t)m_r * FO + chunk * 4);
            v.x = fmaxf(v.x * dv_r + bv.x, 0.f) * t_r;
            v.y = fmaxf(v.y * dv_r + bv.y, 0.f) * t_r;
            v.z = fmaxf(v.z * dv_r + bv.z, 0.f) * t_r;
            v.w = fmaxf(v.w * dv_r + bv.w, 0.f) * t_r;
            *(float4*)(XA + (size_t)nid_r * FO + chunk * 4) = v;
        }
    }
}

// edge remap/compact + next-layer degree; warp-aggregated ecntN atomic
__global__ void k_eremap(const int* __restrict__ srcO, const int* __restrict__ dstO,
                         const int* __restrict__ ecntO, const int* __restrict__ remap,
                         int* __restrict__ srcN, int* __restrict__ dstN,
                         int* __restrict__ ecntN, float* __restrict__ degN) {
    gdep();
    int E = *ecntO;
    int gt = blockIdx.x * blockDim.x + threadIdx.x;
    int lane = threadIdx.x & 31;
    int stride = gridDim.x * blockDim.x;
    for (int e = gt; __any_sync(0xffffffffu, e < E); e += stride) {
        bool in = (e < E);
        int s = -1, d = -1;
        if (in) {
            s = remap[srcO[e]];
            d = remap[dstO[e]];
        }
        bool valid = in && (s >= 0) && (d >= 0);
        unsigned mask = __ballot_sync(0xffffffffu, valid);
        if (!mask) continue;
        int leader = __ffs(mask) - 1;
        int basepos = 0;
        if (lane == leader) basepos = atomicAdd(ecntN, __popc(mask));
        basepos = __shfl_sync(0xffffffffu, basepos, leader);
        if (valid) {
            int pos = basepos + __popc(mask & ((1u << lane) - 1u));
            srcN[pos] = s;
            dstN[pos] = d;
            atomicAdd(&degN[d], 1.f);
        }
    }
}

// readout part 1: partial max/sum over row slices (8 slices per graph)
__global__ void k_read1(const float* __restrict__ X, float* __restrict__ pmax,
                        float* __restrict__ psum, int kn) {
    gdep();
    int b = blockIdx.x >> 3, s = blockIdx.x & 7, f = threadIdx.x;   // 128 threads
    int per = (kn + 7) / 8;
    int i0 = s * per, i1 = min(kn, i0 + per);
    float mx = -3.4e38f, sm = 0.f;
    const float* base = X + (size_t)b * kn * 128 + f;
    for (int i = i0; i < i1; i++) {
        float v = base[(size_t)i * 128];
        mx = fmaxf(mx, v);
        sm += v;
    }
    pmax[blockIdx.x * 128 + f] = mx;
    psum[blockIdx.x * 128 + f] = sm;
}

// readout part 2: final reduce + metadata conv + fc + fc2
__global__ void k_read2(const float* __restrict__ pmax, const float* __restrict__ psum,
                        const float* __restrict__ meta, const float* __restrict__ cw,
                        const float* __restrict__ cb, const float* __restrict__ fcw,
                        const float* __restrict__ fcb, const float* __restrict__ fc2w,
                        const float* __restrict__ fc2b, float* __restrict__ out, int kn) {
    gdep();
    __shared__ float v[260];
    __shared__ float red[128];
    int b = blockIdx.x, f = threadIdx.x;   // 128 threads
    float mx = -3.4e38f, sm = 0.f;
#pragma unroll
    for (int s = 0; s < 8; s++) {
        mx = fmaxf(mx, pmax[(b * 8 + s) * 128 + f]);
        sm += psum[(b * 8 + s) * 128 + f];
    }
    v[f] = mx;
    v[128 + f] = sm / (float)kn;
    if (f < 4) {
        float mv = meta[b] * cw[f] + cb[f];
        v[256 + f] = mv > 0.f ? mv : 0.f;
    }
    __syncthreads();
    float acc = fcb[f];
    for (int i = 0; i < 260; i++) acc += v[i] * fcw[i * 128 + f];
    float hv = acc > 0.f ? acc : 0.f;
    red[f] = hv * fc2w[f];
    __syncthreads();
    for (int s = 64; s > 0; s >>= 1) {
        if (f < s) red[f] += red[f + s];
        __syncthreads();
    }
    if (f == 0) out[b] = red[0] + fc2b[0];
}

// ---------------- host orchestration ----------------
static inline int gdiv(int n, int t) { return (n + t - 1) / t; }

// launch with Programmatic Dependent Launch (overlaps launch latency; the
// consumer kernel's cudaGridDependencySynchronize() enforces data ordering).
// Variadic template helper — immune to commas in template-id kernel names.
template <typename Fn, typename... Args>
static inline void launch_pdl(Fn fn, int grid, int block, Args... args) {
    cudaLaunchConfig_t cfg = {};
    cfg.gridDim = dim3((unsigned)grid);
    cfg.blockDim = dim3((unsigned)block);
    cfg.dynamicSmemBytes = 0;
    cfg.stream = 0;
    cudaLaunchAttribute at[1];
    at[0].id = cudaLaunchAttributeProgrammaticStreamSerialization;
    at[0].val.programmaticStreamSerializationAllowed = 1;
    cfg.attrs = at;
    cfg.numAttrs = 1;
    cudaLaunchKernelEx(&cfg, fn, args...);
}

extern "C" void kernel_launch(void* const* d_in, const int* in_sizes, int n_in,
                              void* d_out, int out_size) {
    const float* x0   = (const float*)d_in[0];
    const int*   ei   = (const int*)  d_in[1];
    const float* meta = (const float*)d_in[2];
    const float* W[4]  = {(const float*)d_in[3], (const float*)d_in[6],
                          (const float*)d_in[9], (const float*)d_in[12]};
    const float* bb[4] = {(const float*)d_in[4], (const float*)d_in[7],
                          (const float*)d_in[10], (const float*)d_in[13]};
    const float* pp[4] = {(const float*)d_in[5], (const float*)d_in[8],
                          (const float*)d_in[11], (const float*)d_in[14]};
    const float* cw   = (const float*)d_in[15];
    const float* cb   = (const float*)d_in[16];
    const float* fcw  = (const float*)d_in[17];
    const float* fcb  = (const float*)d_in[18];
    const float* fc2w = (const float*)d_in[19];
    const float* fc2b = (const float*)d_in[20];
    float* out = (float*)d_out;

    float *H, *XB, *XA, *deg, *score, *pinv, *pmax, *psum;
    unsigned *key, *thresh, *hist12;
    int *remap, *allow, *cntK, *cntE, *srcb, *dstb, *ecnt, *e0c;
    cudaGetSymbolAddress((void**)&H, g_H);
    cudaGetSymbolAddress((void**)&XB, g_XB);
    cudaGetSymbolAddress((void**)&XA, g_XA);
    cudaGetSymbolAddress((void**)&deg, g_deg);
    cudaGetSymbolAddress((void**)&score, g_score);
    cudaGetSymbolAddress((void**)&key, g_key);
    cudaGetSymbolAddress((void**)&remap, g_remap);
    cudaGetSymbolAddress((void**)&srcb, g_srcbuf);
    cudaGetSymbolAddress((void**)&dstb, g_dstbuf);
    cudaGetSymbolAddress((void**)&ecnt, g_ecnt);
    cudaGetSymbolAddress((void**)&e0c, g_E0cnt);
    cudaGetSymbolAddress((void**)&hist12, g_hist12);
    cudaGetSymbolAddress((void**)&thresh, g_thresh);
    cudaGetSymbolAddress((void**)&allow, g_allow);
    cudaGetSymbolAddress((void**)&cntK, g_cntKeep);
    cudaGetSymbolAddress((void**)&cntE, g_cntEq);
    cudaGetSymbolAddress((void**)&pinv, g_pinv);
    cudaGetSymbolAddress((void**)&pmax, g_pmax);
    cudaGetSymbolAddress((void**)&psum, g_psum);

    const int T = 256;

    launch_pdl(k_prep, 256, T, pp[0], pp[1], pp[2], pp[3], pinv, deg, hist12);
    launch_pdl(k_deg0, gdiv(E0C, T), T, ei + E0C, deg);

    for (int i = 0; i < 4; i++) {
        int n = NIN[i], M = BGR * n, k = KK[i];
        const float* Xin = i ? XA : x0;
        const int* eS = i ? (srcb + ((i + 1) & 1) * E0C) : ei;
        const int* eD = i ? (dstb + ((i + 1) & 1) * E0C) : (ei + E0C);
        const int* eC = i ? (ecnt + ((i + 1) & 1)) : e0c;
        int* eSn = srcb + (i & 1) * E0C;
        int* eDn = dstb + (i & 1) * E0C;
        int* eCn = ecnt + (i & 1);

        // 1. H' = XB = (X@W)*dinv (smem-tiled)
        switch (i) {
            case 0: launch_pdl(k_mm<4, 32>,    gdiv(M, 32), T, Xin, W[0], deg, H, XB, M); break;
            case 1: launch_pdl(k_mm<32, 64>,   gdiv(M, 16), T, Xin, W[1], deg, H, XB, M); break;
            case 2: launch_pdl(k_mm<64, 128>,  gdiv(M, 8),  T, Xin, W[2], deg, H, XB, M); break;
            case 3: launch_pdl(k_mm<128, 128>, gdiv(M, 8),  T, Xin, W[3], deg, H, XB, M); break;
        }
        // 2. aggregate: XB[d] += H'[s] (v4 vector RED)
        int aggGrid = (i == 0) ? gdiv(E0C * 8, T) : 4096;
        switch (i) {
            case 0: launch_pdl(k_agg<32>,  aggGrid, T, eS, eD, eC, H, XB); break;
            case 1: launch_pdl(k_agg<64>,  aggGrid, T, eS, eD, eC, H, XB); break;
            case 2: launch_pdl(k_agg<128>, aggGrid, T, eS, eD, eC, H, XB); break;
            case 3: launch_pdl(k_agg<128>, aggGrid, T, eS, eD, eC, H, XB); break;
        }
        // 3. score + key + fused 12-bit histogram (no XB writeback)
        switch (i) {
            case 0: launch_pdl(k_score<32>,  gdiv(M * 32, T), T, XB, deg, bb[0], pp[0], M, n, score, key, hist12); break;
            case 1: launch_pdl(k_score<64>,  gdiv(M * 32, T), T, XB, deg, bb[1], pp[1], M, n, score, key, hist12); break;
            case 2: launch_pdl(k_score<128>, gdiv(M * 32, T), T, XB, deg, bb[2], pp[2], M, n, score, key, hist12); break;
            case 3: launch_pdl(k_score<128>, gdiv(M * 32, T), T, XB, deg, bb[3], pp[3], M, n, score, key, hist12); break;
        }
        // 4. 3-stage select (2 key scans) + zero counters/next deg/next ecnt
        int MN = (i < 3) ? BGR * k : 0;
        launch_pdl(k_select, BGR, 1024, key, n, k, hist12, thresh, allow, cntK, cntE, deg, MN, eCn);
        // 5. compact + gather (finalize applied on kept rows)
        switch (i) {
            case 0: launch_pdl(k_cg<32>,  gdiv(M, T), T, key, score, XB, deg, bb[0], M, n, k,
                               thresh, allow, cntK, cntE, remap, pinv + 0, XA); break;
            case 1: launch_pdl(k_cg<64>,  gdiv(M, T), T, key, score, XB, deg, bb[1], M, n, k,
                               thresh, allow, cntK, cntE, remap, pinv + 1, XA); break;
            case 2: launch_pdl(k_cg<128>, gdiv(M, T), T, key, score, XB, deg, bb[2], M, n, k,
                               thresh, allow, cntK, cntE, remap, pinv + 2, XA); break;
            case 3: launch_pdl(k_cg<128>, gdiv(M, T), T, key, score, XB, deg, bb[3], M, n, k,
                               thresh, allow, cntK, cntE, remap, pinv + 3, XA); break;
        }
        // 6. edge remap + next-layer degree (warp-aggregated count atomic)
        if (i < 3) {
            int erGrid = (i == 0) ? gdiv(E0C, T) : 2048;
            launch_pdl(k_eremap, erGrid, T, eS, eD, eC, remap, eSn, eDn, eCn, deg);
        }
    }

    // readout
    launch_pdl(k_read1, BGR * 8, 128, XA, pmax, psum, KK[3]);
    launch_pdl(k_read2, BGR, 128, pmax, psum, meta, cw, cb, fcw, fcb, fc2w, fc2b, out, KK[3]);
    (void)in_sizes; (void)n_in; (void)out_size;
}